// round 16
// baseline (speedup 1.0000x reference)
#include <cuda_runtime.h>
#include <cuda_fp16.h>

#define BB 16
#define MM 2048
#define NN 2048
#define R  16            // rows per CTA (2 chunks of 8)
#define NLAUNCH 14       // cap (per-batch fused finalize observed ~10-12)
#define PRETOL 2.5e-4f   // per-batch trigger threshold
#define NOTDONE 0x40000000

// Scratch (static __device__ globals -- no runtime allocation)
__device__ __half g_K[(size_t)BB * MM * NN];   // 134 MB fp16 kernel matrix
__device__ float  g_T[3][BB * NN];             // triple-buffered column sums
__device__ float  g_z[BB * MM];                // current z = exp(u)
__device__ float  g_itermax[NLAUNCH][BB];      // per-iteration, PER-BATCH max rel z-change
__device__ int    g_done_b[BB];                // kernel index that finalized each batch

// ---------------------------------------------------------------------------
// T[0] = b (first iteration sees w = b/T = 1, matching v0 = 0), T[1]=T[2]=0,
// distance accumulators = 0, convergence state reset (every graph replay).
// ---------------------------------------------------------------------------
__global__ void init_kernel(const float* __restrict__ b, float* __restrict__ out) {
    int i = blockIdx.x * blockDim.x + threadIdx.x;   // < BB*NN = 32768
    float bv = b[i];
    g_T[0][i] = bv;
    g_T[1][i] = 0.f;
    g_T[2][i] = 0.f;
    if (i < BB) { out[i] = 0.f; g_done_b[i] = NOTDONE; }
    if (i < NLAUNCH * BB) ((float*)g_itermax)[i] = 0.f;
}

// ---------------------------------------------------------------------------
// Fused build + iteration 0.  w == 1 exactly (T[0] = b):
//   read C (fp32) -> K = exp(-10 C) -> write g_K (fp16)
//   S_i = rowsum(K);  z_i = a_i / S_i;  T[1]_j += sum_i K_ij z_i
// Grid: (MM/R, BB) = (128, 16); 512 threads.
// ---------------------------------------------------------------------------
__global__ void __launch_bounds__(512, 3)
sinkhorn_iter0(const float* __restrict__ C, const float* __restrict__ a) {
    __shared__ float part[8 * 128];
    __shared__ float zs[8];

    const int batch = blockIdx.y;
    const int rb    = blockIdx.x;
    const int tid   = threadIdx.x;
    const int warp  = tid >> 5, lane = tid & 31;
    const int row0  = rb * R;

    const float4* srcC = (const float4*)(C + ((size_t)batch * MM + row0) * NN);
    uint2* dstK = (uint2*)(g_K + ((size_t)batch * MM + row0) * NN);
    float a0 = 0.f, a1 = 0.f, a2 = 0.f, a3 = 0.f;

    #pragma unroll
    for (int c = 0; c < 2; c++) {
        uint2 tile[8];
        #pragma unroll
        for (int i = 0; i < 8; i++) {
            float4 cv = srcC[(c * 8 + i) * (NN / 4) + tid];
            float e0 = __expf(-10.f * cv.x), e1 = __expf(-10.f * cv.y);
            float e2 = __expf(-10.f * cv.z), e3 = __expf(-10.f * cv.w);
            __half2 h01 = __floats2half2_rn(e0, e1);
            __half2 h23 = __floats2half2_rn(e2, e3);
            tile[i].x = *(const unsigned*)&h01;
            tile[i].y = *(const unsigned*)&h23;
            dstK[(c * 8 + i) * (NN / 4) + tid] = tile[i];
            float v = e0 + e1 + e2 + e3;       // w == 1
            v += __shfl_xor_sync(0xffffffffu, v, 1);
            v += __shfl_xor_sync(0xffffffffu, v, 2);
            if ((lane & 3) == 0) part[i * 128 + (tid >> 2)] = v;
        }
        __syncthreads();

        if (warp < 8) {
            const float* pp = &part[warp * 128 + lane];
            float s = pp[0] + pp[32] + pp[64] + pp[96];
            s += __shfl_xor_sync(0xffffffffu, s, 16);
            s += __shfl_xor_sync(0xffffffffu, s, 8);
            s += __shfl_xor_sync(0xffffffffu, s, 4);
            s += __shfl_xor_sync(0xffffffffu, s, 2);
            s += __shfl_xor_sync(0xffffffffu, s, 1);
            if (lane == 0) {
                int   ri = batch * MM + row0 + c * 8 + warp;
                float zi = __fdividef(__ldg(&a[ri]), s);
                zs[warp] = zi;
                g_z[ri]  = zi;
            }
        }
        __syncthreads();

        #pragma unroll
        for (int i = 0; i < 8; i++) {
            float zi = zs[i];
            float2 f0 = __half22float2(*(const __half2*)&tile[i].x);
            float2 f1 = __half22float2(*(const __half2*)&tile[i].y);
            a0 += f0.x * zi; a1 += f0.y * zi;
            a2 += f1.x * zi; a3 += f1.y * zi;
        }
    }

    float* To = g_T[1] + batch * NN + 4 * tid;   // outIdx for k=0
    asm volatile("red.global.add.v4.f32 [%0], {%1, %2, %3, %4};"
                 :: "l"(To), "f"(a0), "f"(a1), "f"(a2), "f"(a3)
                 : "memory");
}

// ---------------------------------------------------------------------------
// Kernel k >= 1.  Per-BATCH modes (batches are independent problems):
//   k > g_done_b[batch]:              no-op CTA (batch already finalized)
//   k>=2 && itermax[k-1][batch]<PRETOL: FUSED finalize for this batch --
//       phase 1 computes fresh z from w_in; same register tile then writes
//       P = z_new*K*w_in and accumulates distance = sum P*(-0.1 lnK).
//   else:                             normal iteration for this batch;
//       publishes per-batch max rel z-change via one atomicMax.
// All branch inputs are committed before this launch -> deterministic and
// uniform across each batch's CTAs.
// ---------------------------------------------------------------------------
__global__ void __launch_bounds__(512, 3)
sinkhorn_iter(const float* __restrict__ a, const float* __restrict__ b,
              float* __restrict__ out, int k) {
    const int batch = blockIdx.y;
    if (k > g_done_b[batch]) return;     // this batch already finalized

    const int inIdx   = k % 3;
    const int outIdx  = (k + 1) % 3;
    const int zeroIdx = (k + 2) % 3;
    const bool fin = (k >= 2) && (g_itermax[k - 1][batch] < PRETOL);

    __shared__ float part[8 * 128];
    __shared__ float zs[8];
    __shared__ float dred[16];

    const int rb    = blockIdx.x;
    const int tid   = threadIdx.x;
    const int warp  = tid >> 5, lane = tid & 31;
    const int row0  = rb * R;

    // w for this thread's 4 contiguous columns
    float4 bv = ((const float4*)(b + batch * NN))[tid];
    float4 tv = ((const float4*)(g_T[inIdx] + batch * NN))[tid];
    const float w0 = __fdividef(bv.x, tv.x);
    const float w1 = __fdividef(bv.y, tv.y);
    const float w2 = __fdividef(bv.z, tv.z);
    const float w3 = __fdividef(bv.w, tv.w);

    // Zero next-next T buffer for this batch (only if we keep iterating)
    if (!fin && tid < 16) g_T[zeroIdx][batch * NN + rb * 16 + tid] = 0.f;

    const uint2* src = (const uint2*)(g_K + ((size_t)batch * MM + row0) * NN);
    float a0 = 0.f, a1 = 0.f, a2 = 0.f, a3 = 0.f;
    float dist = 0.f;
    float* P = out + BB;

    #pragma unroll
    for (int c = 0; c < 2; c++) {
        uint2 tile[8];
        #pragma unroll
        for (int i = 0; i < 8; i++)
            tile[i] = src[(c * 8 + i) * (NN / 4) + tid];

        // Phase 1: row dots with w_in, 4-lane pre-reduce
        #pragma unroll
        for (int i = 0; i < 8; i++) {
            float2 f0 = __half22float2(*(const __half2*)&tile[i].x);
            float2 f1 = __half22float2(*(const __half2*)&tile[i].y);
            float v = f0.x * w0 + f0.y * w1 + f1.x * w2 + f1.y * w3;
            v += __shfl_xor_sync(0xffffffffu, v, 1);
            v += __shfl_xor_sync(0xffffffffu, v, 2);
            if ((lane & 3) == 0) part[i * 128 + (tid >> 2)] = v;
        }
        __syncthreads();

        // One warp per row: S_i -> z_i (fresh, from w_in)
        if (warp < 8) {
            const float* pp = &part[warp * 128 + lane];
            float s = pp[0] + pp[32] + pp[64] + pp[96];
            s += __shfl_xor_sync(0xffffffffu, s, 16);
            s += __shfl_xor_sync(0xffffffffu, s, 8);
            s += __shfl_xor_sync(0xffffffffu, s, 4);
            s += __shfl_xor_sync(0xffffffffu, s, 2);
            s += __shfl_xor_sync(0xffffffffu, s, 1);
            if (lane == 0) {
                int   ri = batch * MM + row0 + c * 8 + warp;
                float zp = g_z[ri];
                float zi = __fdividef(__ldg(&a[ri]), s);
                zs[warp] = zi;
                g_z[ri]  = zi;
                dred[c * 8 + warp] = fabsf(__fdividef(zi, zp) - 1.f);
            }
        }
        __syncthreads();

        if (fin) {
            // FUSED finalize: P = z_new * K * w_in, distance from C = -0.1 lnK
            #pragma unroll
            for (int i = 0; i < 8; i++) {
                float zi = zs[i];
                float2 f0 = __half22float2(*(const __half2*)&tile[i].x);
                float2 f1 = __half22float2(*(const __half2*)&tile[i].y);
                float p0 = zi * f0.x * w0, p1 = zi * f0.y * w1;
                float p2 = zi * f1.x * w2, p3 = zi * f1.y * w3;
                ((float4*)(P + ((size_t)batch * MM + row0 + c * 8 + i) * NN))[tid] =
                    make_float4(p0, p1, p2, p3);
                dist += p0 * __logf(f0.x) + p1 * __logf(f0.y)
                      + p2 * __logf(f1.x) + p3 * __logf(f1.y);
            }
        } else {
            // Phase 2: column partials from the same registers
            #pragma unroll
            for (int i = 0; i < 8; i++) {
                float zi = zs[i];
                float2 f0 = __half22float2(*(const __half2*)&tile[i].x);
                float2 f1 = __half22float2(*(const __half2*)&tile[i].y);
                a0 += f0.x * zi; a1 += f0.y * zi;
                a2 += f1.x * zi; a3 += f1.y * zi;
            }
        }
    }

    if (fin) {
        dist *= -0.1f;
        #pragma unroll
        for (int off = 16; off; off >>= 1)
            dist += __shfl_xor_sync(0xffffffffu, dist, off);
        __shared__ float rbuf[16];
        if (lane == 0) rbuf[warp] = dist;
        __syncthreads();
        if (tid == 0) {
            float s = 0.f;
            #pragma unroll
            for (int q = 0; q < 16; q++) s += rbuf[q];
            atomicAdd(&out[batch], s);
            g_done_b[batch] = k;         // same value from all this batch's CTAs
        }
        return;
    }

    float* To = g_T[outIdx] + batch * NN + 4 * tid;
    asm volatile("red.global.add.v4.f32 [%0], {%1, %2, %3, %4};"
                 :: "l"(To), "f"(a0), "f"(a1), "f"(a2), "f"(a3)
                 : "memory");

    // Publish per-batch max rel z-change (order-independent atomicMax)
    if (tid == 0) {
        float m = dred[0];
        #pragma unroll
        for (int q = 1; q < 16; q++) m = fmaxf(m, dred[q]);
        atomicMax((int*)&g_itermax[k][batch], __float_as_int(m));  // m >= 0
    }
}

// ---------------------------------------------------------------------------
// FALLBACK finalize, per batch (only for batches that never triggered):
// P from resident fp16 K with w = b/T[NLAUNCH%3], z from g_z; C = -0.1 lnK.
// Grid: (MM/8, BB); 256 threads.
// ---------------------------------------------------------------------------
__global__ void __launch_bounds__(256)
finalize_kernel(const float* __restrict__ b, float* __restrict__ out) {
    const int batch = blockIdx.y;
    if (g_done_b[batch] != NOTDONE) return;   // this batch already finalized

    const int rb    = blockIdx.x;
    const int tid   = threadIdx.x;
    const int tIdx  = NLAUNCH % 3;            // buffer written by kernel NLAUNCH-1

    const float4* b4 = (const float4*)(b + batch * NN);
    const float4* t4 = (const float4*)(g_T[tIdx] + batch * NN);
    float4 bv0 = b4[2 * tid], bv1 = b4[2 * tid + 1];
    float4 tv0 = t4[2 * tid], tv1 = t4[2 * tid + 1];
    float w[8];
    w[0] = bv0.x / tv0.x; w[1] = bv0.y / tv0.y;
    w[2] = bv0.z / tv0.z; w[3] = bv0.w / tv0.w;
    w[4] = bv1.x / tv1.x; w[5] = bv1.y / tv1.y;
    w[6] = bv1.z / tv1.z; w[7] = bv1.w / tv1.w;

    const size_t rowbase = (size_t)batch * MM + rb * 8;
    float* P = out + BB;
    float acc = 0.f;

    #pragma unroll
    for (int i = 0; i < 8; i++) {
        float zi = g_z[rowbase + i];
        uint4 kk = ((const uint4*)(g_K + (rowbase + i) * NN))[tid];
        const __half2* h = (const __half2*)&kk;
        float kf[8];
        {
            float2 f0 = __half22float2(h[0]);
            float2 f1 = __half22float2(h[1]);
            float2 f2 = __half22float2(h[2]);
            float2 f3 = __half22float2(h[3]);
            kf[0] = f0.x; kf[1] = f0.y; kf[2] = f1.x; kf[3] = f1.y;
            kf[4] = f2.x; kf[5] = f2.y; kf[6] = f3.x; kf[7] = f3.y;
        }
        float p[8];
        #pragma unroll
        for (int q = 0; q < 8; q++) {
            p[q] = zi * kf[q] * w[q];
            acc += p[q] * (-0.1f) * __logf(kf[q]);
        }
        float4* Prow = (float4*)(P + (rowbase + i) * NN);
        Prow[2 * tid]     = make_float4(p[0], p[1], p[2], p[3]);
        Prow[2 * tid + 1] = make_float4(p[4], p[5], p[6], p[7]);
    }

    #pragma unroll
    for (int off = 16; off; off >>= 1)
        acc += __shfl_xor_sync(0xffffffffu, acc, off);
    __shared__ float rbuf[8];
    int warp = tid >> 5, lane = tid & 31;
    if (lane == 0) rbuf[warp] = acc;
    __syncthreads();
    if (tid == 0) {
        float s = 0.f;
        #pragma unroll
        for (int q = 0; q < 8; q++) s += rbuf[q];
        atomicAdd(&out[batch], s);
    }
}

// ---------------------------------------------------------------------------
extern "C" void kernel_launch(void* const* d_in, const int* in_sizes, int n_in,
                              void* d_out, int out_size) {
    const float* C = (const float*)d_in[0];   // (16, 2048, 2048)
    const float* a = (const float*)d_in[1];   // (16, 2048)
    const float* b = (const float*)d_in[2];   // (16, 2048)
    float* out = (float*)d_out;               // [0..16) distance, [16..) P

    init_kernel<<<(BB * NN) / 256, 256>>>(b, out);
    sinkhorn_iter0<<<dim3(MM / R, BB), 512>>>(C, a);
    for (int k = 1; k < NLAUNCH; k++)
        sinkhorn_iter<<<dim3(MM / R, BB), 512>>>(a, b, out, k);

    finalize_kernel<<<dim3(MM / 8, BB), 256>>>(b, out);
}

// round 17
// speedup vs baseline: 1.1550x; 1.1550x over previous
#include <cuda_runtime.h>
#include <cuda_fp16.h>

#define BB 16
#define MM 2048
#define NN 2048
#define R  16            // rows per CTA (2 chunks of 8)
#define NLAUNCH 13       // cap (per-batch fused finalize expected ~10-11)
#define PRETOL 5e-4f     // per-batch trigger threshold (one iter earlier)
#define NOTDONE 0x40000000

// Scratch (static __device__ globals -- no runtime allocation)
__device__ __half g_K[(size_t)BB * MM * NN];   // 134 MB fp16 kernel matrix
__device__ float  g_T[3][BB * NN];             // triple-buffered column sums
__device__ float  g_z[BB * MM];                // current z = exp(u)
__device__ float  g_itermax[NLAUNCH][BB];      // per-iteration, PER-BATCH max rel z-change
__device__ int    g_done_b[BB];                // kernel index that finalized each batch

// ---------------------------------------------------------------------------
// T[0] = b (first iteration sees w = b/T = 1, matching v0 = 0), T[1]=T[2]=0,
// distance accumulators = 0, convergence state reset (every graph replay).
// ---------------------------------------------------------------------------
__global__ void init_kernel(const float* __restrict__ b, float* __restrict__ out) {
    int i = blockIdx.x * blockDim.x + threadIdx.x;   // < BB*NN = 32768
    float bv = b[i];
    g_T[0][i] = bv;
    g_T[1][i] = 0.f;
    g_T[2][i] = 0.f;
    if (i < BB) { out[i] = 0.f; g_done_b[i] = NOTDONE; }
    if (i < NLAUNCH * BB) ((float*)g_itermax)[i] = 0.f;
}

// ---------------------------------------------------------------------------
// Fused build + iteration 0.  w == 1 exactly (T[0] = b):
//   read C (fp32, streaming) -> K = exp(-10 C) -> write g_K (fp16, streaming)
//   S_i = rowsum(K);  z_i = a_i / S_i;  T[1]_j += sum_i K_ij z_i
// Grid: (MM/R, BB) = (128, 16); 512 threads.
// ---------------------------------------------------------------------------
__global__ void __launch_bounds__(512, 3)
sinkhorn_iter0(const float* __restrict__ C, const float* __restrict__ a) {
    __shared__ float part[8 * 128];
    __shared__ float zs[8];

    const int batch = blockIdx.y;
    const int rb    = blockIdx.x;
    const int tid   = threadIdx.x;
    const int warp  = tid >> 5, lane = tid & 31;
    const int row0  = rb * R;

    const float4* srcC = (const float4*)(C + ((size_t)batch * MM + row0) * NN);
    uint2* dstK = (uint2*)(g_K + ((size_t)batch * MM + row0) * NN);
    float a0 = 0.f, a1 = 0.f, a2 = 0.f, a3 = 0.f;

    #pragma unroll
    for (int c = 0; c < 2; c++) {
        uint2 tile[8];
        #pragma unroll
        for (int i = 0; i < 8; i++) {
            float4 cv = __ldcs(&srcC[(c * 8 + i) * (NN / 4) + tid]);  // stream C
            float e0 = __expf(-10.f * cv.x), e1 = __expf(-10.f * cv.y);
            float e2 = __expf(-10.f * cv.z), e3 = __expf(-10.f * cv.w);
            __half2 h01 = __floats2half2_rn(e0, e1);
            __half2 h23 = __floats2half2_rn(e2, e3);
            tile[i].x = *(const unsigned*)&h01;
            tile[i].y = *(const unsigned*)&h23;
            __stcs(&dstK[(c * 8 + i) * (NN / 4) + tid], tile[i]);     // stream K
            float v = e0 + e1 + e2 + e3;       // w == 1
            v += __shfl_xor_sync(0xffffffffu, v, 1);
            v += __shfl_xor_sync(0xffffffffu, v, 2);
            if ((lane & 3) == 0) part[i * 128 + (tid >> 2)] = v;
        }
        __syncthreads();

        if (warp < 8) {
            const float* pp = &part[warp * 128 + lane];
            float s = pp[0] + pp[32] + pp[64] + pp[96];
            s += __shfl_xor_sync(0xffffffffu, s, 16);
            s += __shfl_xor_sync(0xffffffffu, s, 8);
            s += __shfl_xor_sync(0xffffffffu, s, 4);
            s += __shfl_xor_sync(0xffffffffu, s, 2);
            s += __shfl_xor_sync(0xffffffffu, s, 1);
            if (lane == 0) {
                int   ri = batch * MM + row0 + c * 8 + warp;
                float zi = __fdividef(__ldg(&a[ri]), s);
                zs[warp] = zi;
                g_z[ri]  = zi;
            }
        }
        __syncthreads();

        #pragma unroll
        for (int i = 0; i < 8; i++) {
            float zi = zs[i];
            float2 f0 = __half22float2(*(const __half2*)&tile[i].x);
            float2 f1 = __half22float2(*(const __half2*)&tile[i].y);
            a0 += f0.x * zi; a1 += f0.y * zi;
            a2 += f1.x * zi; a3 += f1.y * zi;
        }
    }

    float* To = g_T[1] + batch * NN + 4 * tid;   // outIdx for k=0
    asm volatile("red.global.add.v4.f32 [%0], {%1, %2, %3, %4};"
                 :: "l"(To), "f"(a0), "f"(a1), "f"(a2), "f"(a3)
                 : "memory");
}

// ---------------------------------------------------------------------------
// Kernel k >= 1.  Per-BATCH modes (batches are independent problems):
//   k > g_done_b[batch]:                no-op CTA (batch already finalized)
//   k>=2 && itermax[k-1][batch]<PRETOL: FUSED finalize for this batch --
//       phase 1 computes fresh z from w_in; same register tile then writes
//       P = z_new*K*w_in (streaming stores) and accumulates
//       distance = sum P*(-0.1 lnK).
//   else:                               normal iteration for this batch;
//       publishes per-batch max rel z-change via one atomicMax.
// All branch inputs are committed before this launch -> deterministic and
// uniform across each batch's CTAs.
// ---------------------------------------------------------------------------
__global__ void __launch_bounds__(512, 3)
sinkhorn_iter(const float* __restrict__ a, const float* __restrict__ b,
              float* __restrict__ out, int k) {
    const int batch = blockIdx.y;
    if (k > g_done_b[batch]) return;     // this batch already finalized

    const int inIdx   = k % 3;
    const int outIdx  = (k + 1) % 3;
    const int zeroIdx = (k + 2) % 3;
    const bool fin = (k >= 2) && (g_itermax[k - 1][batch] < PRETOL);

    __shared__ float part[8 * 128];
    __shared__ float zs[8];
    __shared__ float dred[16];

    const int rb    = blockIdx.x;
    const int tid   = threadIdx.x;
    const int warp  = tid >> 5, lane = tid & 31;
    const int row0  = rb * R;

    // w for this thread's 4 contiguous columns
    float4 bv = ((const float4*)(b + batch * NN))[tid];
    float4 tv = ((const float4*)(g_T[inIdx] + batch * NN))[tid];
    const float w0 = __fdividef(bv.x, tv.x);
    const float w1 = __fdividef(bv.y, tv.y);
    const float w2 = __fdividef(bv.z, tv.z);
    const float w3 = __fdividef(bv.w, tv.w);

    // Zero next-next T buffer for this batch (only if we keep iterating)
    if (!fin && tid < 16) g_T[zeroIdx][batch * NN + rb * 16 + tid] = 0.f;

    const uint2* src = (const uint2*)(g_K + ((size_t)batch * MM + row0) * NN);
    float a0 = 0.f, a1 = 0.f, a2 = 0.f, a3 = 0.f;
    float dist = 0.f;
    float* P = out + BB;

    #pragma unroll
    for (int c = 0; c < 2; c++) {
        uint2 tile[8];
        #pragma unroll
        for (int i = 0; i < 8; i++)
            tile[i] = src[(c * 8 + i) * (NN / 4) + tid];

        // Phase 1: row dots with w_in, 4-lane pre-reduce
        #pragma unroll
        for (int i = 0; i < 8; i++) {
            float2 f0 = __half22float2(*(const __half2*)&tile[i].x);
            float2 f1 = __half22float2(*(const __half2*)&tile[i].y);
            float v = f0.x * w0 + f0.y * w1 + f1.x * w2 + f1.y * w3;
            v += __shfl_xor_sync(0xffffffffu, v, 1);
            v += __shfl_xor_sync(0xffffffffu, v, 2);
            if ((lane & 3) == 0) part[i * 128 + (tid >> 2)] = v;
        }
        __syncthreads();

        // One warp per row: S_i -> z_i (fresh, from w_in)
        if (warp < 8) {
            const float* pp = &part[warp * 128 + lane];
            float s = pp[0] + pp[32] + pp[64] + pp[96];
            s += __shfl_xor_sync(0xffffffffu, s, 16);
            s += __shfl_xor_sync(0xffffffffu, s, 8);
            s += __shfl_xor_sync(0xffffffffu, s, 4);
            s += __shfl_xor_sync(0xffffffffu, s, 2);
            s += __shfl_xor_sync(0xffffffffu, s, 1);
            if (lane == 0) {
                int   ri = batch * MM + row0 + c * 8 + warp;
                float zp = g_z[ri];
                float zi = __fdividef(__ldg(&a[ri]), s);
                zs[warp] = zi;
                g_z[ri]  = zi;
                dred[c * 8 + warp] = fabsf(__fdividef(zi, zp) - 1.f);
            }
        }
        __syncthreads();

        if (fin) {
            // FUSED finalize: P = z_new * K * w_in, distance from C = -0.1 lnK
            #pragma unroll
            for (int i = 0; i < 8; i++) {
                float zi = zs[i];
                float2 f0 = __half22float2(*(const __half2*)&tile[i].x);
                float2 f1 = __half22float2(*(const __half2*)&tile[i].y);
                float p0 = zi * f0.x * w0, p1 = zi * f0.y * w1;
                float p2 = zi * f1.x * w2, p3 = zi * f1.y * w3;
                __stcs((float4*)(P + ((size_t)batch * MM + row0 + c * 8 + i) * NN) + tid,
                       make_float4(p0, p1, p2, p3));          // stream P
                dist += p0 * __logf(f0.x) + p1 * __logf(f0.y)
                      + p2 * __logf(f1.x) + p3 * __logf(f1.y);
            }
        } else {
            // Phase 2: column partials from the same registers
            #pragma unroll
            for (int i = 0; i < 8; i++) {
                float zi = zs[i];
                float2 f0 = __half22float2(*(const __half2*)&tile[i].x);
                float2 f1 = __half22float2(*(const __half2*)&tile[i].y);
                a0 += f0.x * zi; a1 += f0.y * zi;
                a2 += f1.x * zi; a3 += f1.y * zi;
            }
        }
    }

    if (fin) {
        dist *= -0.1f;
        #pragma unroll
        for (int off = 16; off; off >>= 1)
            dist += __shfl_xor_sync(0xffffffffu, dist, off);
        __shared__ float rbuf[16];
        if (lane == 0) rbuf[warp] = dist;
        __syncthreads();
        if (tid == 0) {
            float s = 0.f;
            #pragma unroll
            for (int q = 0; q < 16; q++) s += rbuf[q];
            atomicAdd(&out[batch], s);
            g_done_b[batch] = k;         // same value from all this batch's CTAs
        }
        return;
    }

    float* To = g_T[outIdx] + batch * NN + 4 * tid;
    asm volatile("red.global.add.v4.f32 [%0], {%1, %2, %3, %4};"
                 :: "l"(To), "f"(a0), "f"(a1), "f"(a2), "f"(a3)
                 : "memory");

    // Publish per-batch max rel z-change (order-independent atomicMax)
    if (tid == 0) {
        float m = dred[0];
        #pragma unroll
        for (int q = 1; q < 16; q++) m = fmaxf(m, dred[q]);
        atomicMax((int*)&g_itermax[k][batch], __float_as_int(m));  // m >= 0
    }
}

// ---------------------------------------------------------------------------
// FALLBACK finalize, per batch (only for batches that never triggered):
// P from resident fp16 K with w = b/T[NLAUNCH%3], z from g_z; C = -0.1 lnK.
// Grid: (MM/8, BB); 256 threads.
// ---------------------------------------------------------------------------
__global__ void __launch_bounds__(256)
finalize_kernel(const float* __restrict__ b, float* __restrict__ out) {
    const int batch = blockIdx.y;
    if (g_done_b[batch] != NOTDONE) return;   // this batch already finalized

    const int rb    = blockIdx.x;
    const int tid   = threadIdx.x;
    const int tIdx  = NLAUNCH % 3;            // buffer written by kernel NLAUNCH-1

    const float4* b4 = (const float4*)(b + batch * NN);
    const float4* t4 = (const float4*)(g_T[tIdx] + batch * NN);
    float4 bv0 = b4[2 * tid], bv1 = b4[2 * tid + 1];
    float4 tv0 = t4[2 * tid], tv1 = t4[2 * tid + 1];
    float w[8];
    w[0] = bv0.x / tv0.x; w[1] = bv0.y / tv0.y;
    w[2] = bv0.z / tv0.z; w[3] = bv0.w / tv0.w;
    w[4] = bv1.x / tv1.x; w[5] = bv1.y / tv1.y;
    w[6] = bv1.z / tv1.z; w[7] = bv1.w / tv1.w;

    const size_t rowbase = (size_t)batch * MM + rb * 8;
    float* P = out + BB;
    float acc = 0.f;

    #pragma unroll
    for (int i = 0; i < 8; i++) {
        float zi = g_z[rowbase + i];
        uint4 kk = ((const uint4*)(g_K + (rowbase + i) * NN))[tid];
        const __half2* h = (const __half2*)&kk;
        float kf[8];
        {
            float2 f0 = __half22float2(h[0]);
            float2 f1 = __half22float2(h[1]);
            float2 f2 = __half22float2(h[2]);
            float2 f3 = __half22float2(h[3]);
            kf[0] = f0.x; kf[1] = f0.y; kf[2] = f1.x; kf[3] = f1.y;
            kf[4] = f2.x; kf[5] = f2.y; kf[6] = f3.x; kf[7] = f3.y;
        }
        float p[8];
        #pragma unroll
        for (int q = 0; q < 8; q++) {
            p[q] = zi * kf[q] * w[q];
            acc += p[q] * (-0.1f) * __logf(kf[q]);
        }
        float4* Prow = (float4*)(P + (rowbase + i) * NN);
        __stcs(&Prow[2 * tid],     make_float4(p[0], p[1], p[2], p[3]));
        __stcs(&Prow[2 * tid + 1], make_float4(p[4], p[5], p[6], p[7]));
    }

    #pragma unroll
    for (int off = 16; off; off >>= 1)
        acc += __shfl_xor_sync(0xffffffffu, acc, off);
    __shared__ float rbuf[8];
    int warp = tid >> 5, lane = tid & 31;
    if (lane == 0) rbuf[warp] = acc;
    __syncthreads();
    if (tid == 0) {
        float s = 0.f;
        #pragma unroll
        for (int q = 0; q < 8; q++) s += rbuf[q];
        atomicAdd(&out[batch], s);
    }
}

// ---------------------------------------------------------------------------
extern "C" void kernel_launch(void* const* d_in, const int* in_sizes, int n_in,
                              void* d_out, int out_size) {
    const float* C = (const float*)d_in[0];   // (16, 2048, 2048)
    const float* a = (const float*)d_in[1];   // (16, 2048)
    const float* b = (const float*)d_in[2];   // (16, 2048)
    float* out = (float*)d_out;               // [0..16) distance, [16..) P

    init_kernel<<<(BB * NN) / 256, 256>>>(b, out);
    sinkhorn_iter0<<<dim3(MM / R, BB), 512>>>(C, a);
    for (int k = 1; k < NLAUNCH; k++)
        sinkhorn_iter<<<dim3(MM / R, BB), 512>>>(a, b, out, k);

    finalize_kernel<<<dim3(MM / 8, BB), 256>>>(b, out);
}